// round 4
// baseline (speedup 1.0000x reference)
#include <cuda_runtime.h>
#include <math.h>
#include <stdint.h>

#define NN 50000
#define DD 128
#define GG 8
#define EPSV 1e-5f

typedef unsigned long long ull;

// ---------------- scratch (static device globals; no allocation) ----------------
__device__ float g_agg[(size_t)NN * DD];   // neighbor sum
__device__ float g_f[(size_t)NN * DD];     // post-GELU features
__device__ float g_deg[NN];
__device__ float g_inv[NN];
__device__ float g_sumf[GG * DD];
__device__ float g_sumf2[GG * DD];
__device__ float g_cnt[GG];
__device__ float g_scaleA[GG * DD];
__device__ float g_shiftB[GG * DD];

// ---------------- K0: zero scratch ----------------
__global__ void k_zero() {
    int i = blockIdx.x * blockDim.x + threadIdx.x;
    if (i < NN * 32) ((float4*)g_agg)[i] = make_float4(0.f, 0.f, 0.f, 0.f);
    if (i < NN) g_deg[i] = 0.f;
    if (i < GG * DD) { g_sumf[i] = 0.f; g_sumf2[i] = 0.f; }
    if (i < GG) g_cnt[i] = 0.f;
}

// ---------------- K1: edge scatter (1 warp per edge, vector RED) ----------------
__global__ void k_edges(const float* __restrict__ x, const int* __restrict__ ei, int E) {
    int w = (blockIdx.x * blockDim.x + threadIdx.x) >> 5;
    int lane = threadIdx.x & 31;
    if (w >= E) return;
    int s = __ldg(&ei[w]);
    int d = __ldg(&ei[E + w]);
    float4 v = __ldg(&((const float4*)x)[(size_t)s * 32 + lane]);
    float* a = &g_agg[(size_t)d * DD + lane * 4];
    asm volatile("red.global.add.v4.f32 [%0], {%1,%2,%3,%4};"
                 :: "l"(a), "f"(v.x), "f"(v.y), "f"(v.z), "f"(v.w) : "memory");
    if (lane == 0) atomicAdd(&g_deg[d], 1.0f);
}

// ---------------- K2: inverse degree + per-graph counts ----------------
__global__ void k_prep(const int* __restrict__ batch, int n) {
    __shared__ int hist[GG];
    if (threadIdx.x < GG) hist[threadIdx.x] = 0;
    __syncthreads();
    int i = blockIdx.x * blockDim.x + threadIdx.x;
    if (i < n) {
        g_inv[i] = 1.0f / fmaxf(g_deg[i], 1.0f);
        atomicAdd(&hist[batch[i]], 1);
    }
    __syncthreads();
    if (threadIdx.x < GG && hist[threadIdx.x] > 0)
        atomicAdd(&g_cnt[threadIdx.x], (float)hist[threadIdx.x]);
}

// ---------------- K3: fused GEMM (K=256: [agg/deg | x] @ [Wl | Wr]^T)
// f32x2 packed FMA (FFMA2) + register double-buffered staging.
// Tile: 128 rows x 128 cols, 256 threads, 8x8 register blocking per thread.
#define LDT 132

__global__ __launch_bounds__(256) void k_gemm(
    const float* __restrict__ x, const float* __restrict__ Wl,
    const float* __restrict__ bl, const float* __restrict__ Wr,
    const int* __restrict__ batch, int n)
{
    __shared__ float sA[32 * LDT];
    __shared__ float sW[32 * LDT];

    const int tid = threadIdx.x;
    const int tx = tid & 15;          // col group: cols tx*8 .. tx*8+7
    const int ty = tid >> 4;          // row group: rows ty*8 .. ty*8+7
    const int row0 = blockIdx.x * 128;
    const int kv = tid & 7;           // float4 index within 32-k chunk
    const int rb = tid >> 3;          // 0..31

    // Packed accumulators: acc2[i][jp] = (C[i][2jp], C[i][2jp+1])
    ull acc2[8][4];
#pragma unroll
    for (int i = 0; i < 8; ++i)
#pragma unroll
        for (int jp = 0; jp < 4; ++jp) acc2[i][jp] = 0ULL;

    // Prefetch registers for one chunk (4 row-slices x (data, weight))
    float4 pv[4], pw[4];

    // ---- load chunk kc into registers (inv-scale applied for agg chunks) ----
    auto load_chunk = [&](int kc) {
        const bool isA = (kc < 4);
        const int kq = (kc & 3) * 8;
#pragma unroll
        for (int p = 0; p < 4; ++p) {
            int r = rb + p * 32;
            int gr = row0 + r;
            float4 v = make_float4(0.f, 0.f, 0.f, 0.f);
            if (gr < n) {
                if (isA) {
                    v = __ldg(&((const float4*)g_agg)[(size_t)gr * 32 + kq + kv]);
                    float iv = g_inv[gr];
                    v.x *= iv; v.y *= iv; v.z *= iv; v.w *= iv;
                } else {
                    v = __ldg(&((const float4*)x)[(size_t)gr * 32 + kq + kv]);
                }
            }
            pv[p] = v;
            const float4* Wsrc = isA ? (const float4*)Wl : (const float4*)Wr;
            pw[p] = __ldg(&Wsrc[(size_t)r * 32 + kq + kv]);
        }
    };

    load_chunk(0);

    for (int kc = 0; kc < 8; ++kc) {
        __syncthreads();
#pragma unroll
        for (int p = 0; p < 4; ++p) {
            int r = rb + p * 32;
            int kb = kv * 4;
            sA[(kb + 0) * LDT + r] = pv[p].x; sA[(kb + 1) * LDT + r] = pv[p].y;
            sA[(kb + 2) * LDT + r] = pv[p].z; sA[(kb + 3) * LDT + r] = pv[p].w;
            sW[(kb + 0) * LDT + r] = pw[p].x; sW[(kb + 1) * LDT + r] = pw[p].y;
            sW[(kb + 2) * LDT + r] = pw[p].z; sW[(kb + 3) * LDT + r] = pw[p].w;
        }
        __syncthreads();

        // Prefetch next chunk while computing this one (LDG latency overlap)
        if (kc < 7) load_chunk(kc + 1);

#pragma unroll
        for (int k = 0; k < 32; ++k) {
            const float* pa = sA + k * LDT + ty * 8;
            const float* pwv = sW + k * LDT + tx * 8;
            float4 A0 = *(const float4*)(pa);      float4 A1 = *(const float4*)(pa + 4);
            float4 W0 = *(const float4*)(pwv);     float4 W1 = *(const float4*)(pwv + 4);
            float av[8] = {A0.x, A0.y, A0.z, A0.w, A1.x, A1.y, A1.z, A1.w};
            // w j-pairs packed straight from the vector loads
            ull w2[4];
            asm("mov.b64 %0, {%1, %2};" : "=l"(w2[0]) : "f"(W0.x), "f"(W0.y));
            asm("mov.b64 %0, {%1, %2};" : "=l"(w2[1]) : "f"(W0.z), "f"(W0.w));
            asm("mov.b64 %0, {%1, %2};" : "=l"(w2[2]) : "f"(W1.x), "f"(W1.y));
            asm("mov.b64 %0, {%1, %2};" : "=l"(w2[3]) : "f"(W1.z), "f"(W1.w));
#pragma unroll
            for (int i = 0; i < 8; ++i) {
                ull a2;
                asm("mov.b64 %0, {%1, %1};" : "=l"(a2) : "f"(av[i]));
#pragma unroll
                for (int jp = 0; jp < 4; ++jp)
                    asm("fma.rn.f32x2 %0, %1, %2, %0;"
                        : "+l"(acc2[i][jp]) : "l"(a2), "l"(w2[jp]));
            }
        }
    }

    // ---- unpack accumulators ----
    float acc[8][8];
#pragma unroll
    for (int i = 0; i < 8; ++i)
#pragma unroll
        for (int jp = 0; jp < 4; ++jp) {
            float lo, hi;
            asm("mov.b64 {%0, %1}, %2;" : "=f"(lo), "=f"(hi) : "l"(acc2[i][jp]));
            acc[i][2 * jp] = lo; acc[i][2 * jp + 1] = hi;
        }

    // ---- epilogue: bias + exact GELU + store f + per-graph sum/sum2 ----
    float4 b0 = __ldg(&((const float4*)bl)[tx * 2]);
    float4 b1 = __ldg(&((const float4*)bl)[tx * 2 + 1]);
    float bb[8] = {b0.x, b0.y, b0.z, b0.w, b1.x, b1.y, b1.z, b1.w};

    float sf[8], sf2[8];
#pragma unroll
    for (int j = 0; j < 8; ++j) { sf[j] = 0.f; sf2[j] = 0.f; }
    int gprev = -1;

#pragma unroll
    for (int i = 0; i < 8; ++i) {
        int r = row0 + ty * 8 + i;
        if (r < n) {
            int g = batch[r];
            if (g != gprev) {
                if (gprev >= 0) {
#pragma unroll
                    for (int j = 0; j < 8; ++j) {
                        atomicAdd(&g_sumf[gprev * DD + tx * 8 + j], sf[j]);
                        atomicAdd(&g_sumf2[gprev * DD + tx * 8 + j], sf2[j]);
                        sf[j] = 0.f; sf2[j] = 0.f;
                    }
                }
                gprev = g;
            }
            float fv[8];
#pragma unroll
            for (int j = 0; j < 8; ++j) {
                float v = acc[i][j] + bb[j];
                v = 0.5f * v * (1.0f + erff(v * 0.70710678118654752f));
                fv[j] = v;
                sf[j] += v;
                sf2[j] += v * v;
            }
            float4 o0 = make_float4(fv[0], fv[1], fv[2], fv[3]);
            float4 o1 = make_float4(fv[4], fv[5], fv[6], fv[7]);
            ((float4*)g_f)[(size_t)r * 32 + tx * 2] = o0;
            ((float4*)g_f)[(size_t)r * 32 + tx * 2 + 1] = o1;
        }
    }
    if (gprev >= 0) {
#pragma unroll
        for (int j = 0; j < 8; ++j) {
            atomicAdd(&g_sumf[gprev * DD + tx * 8 + j], sf[j]);
            atomicAdd(&g_sumf2[gprev * DD + tx * 8 + j], sf2[j]);
        }
    }
}

// ---------------- K4: fold stats into per-(graph,col) scale/shift ----------------
__global__ void k_norm(const float* __restrict__ gw, const float* __restrict__ gb,
                       const float* __restrict__ ms) {
    int i = threadIdx.x;              // 1024 = G*D
    int c = i & 127;
    int g = i >> 7;
    float cnt = fmaxf(g_cnt[g], 1.0f);
    float m = g_sumf[i] / cnt;
    float e2 = g_sumf2[i] / cnt;
    float s = ms[c];
    float var = e2 - (2.0f * s - s * s) * m * m;   // E[(f - s*m)^2]
    var = fmaxf(var, 0.0f);
    float inv = rsqrtf(var + EPSV);
    float w = gw[c];
    g_scaleA[i] = inv * w;
    g_shiftB[i] = gb[c] - s * m * inv * w;
}

// ---------------- K5: out = f*scaleA + shiftB + x ----------------
__global__ void k_out(const float* __restrict__ x, const int* __restrict__ batch,
                      float* __restrict__ out, int n) {
    int i = blockIdx.x * blockDim.x + threadIdx.x;
    if (i >= n * 32) return;
    int row = i >> 5;
    int c4 = i & 31;
    int g = batch[row];                       // uniform per warp (1 warp == 1 row)
    float4 f = ((const float4*)g_f)[i];
    float4 s = __ldg(&((const float4*)g_scaleA)[g * 32 + c4]);
    float4 b = __ldg(&((const float4*)g_shiftB)[g * 32 + c4]);
    float4 xv = ((const float4*)x)[i];
    float4 o;
    o.x = fmaf(f.x, s.x, b.x) + xv.x;
    o.y = fmaf(f.y, s.y, b.y) + xv.y;
    o.z = fmaf(f.z, s.z, b.z) + xv.z;
    o.w = fmaf(f.w, s.w, b.w) + xv.w;
    ((float4*)out)[i] = o;
}

// ---------------- host launcher ----------------
extern "C" void kernel_launch(void* const* d_in, const int* in_sizes, int n_in,
                              void* d_out, int out_size) {
    const float* x     = (const float*)d_in[0];
    const int*   ei    = (const int*)d_in[1];
    const int*   batch = (const int*)d_in[2];
    // d_in[3] = num_graphs (fixed G=8)
    const float* Wl = (const float*)d_in[4];
    const float* bl = (const float*)d_in[5];
    const float* Wr = (const float*)d_in[6];
    const float* gw = (const float*)d_in[7];
    const float* gb = (const float*)d_in[8];
    const float* ms = (const float*)d_in[9];

    int n = in_sizes[0] / DD;
    int E = in_sizes[1] / 2;

    k_zero<<<(NN * 32 + 255) / 256, 256>>>();
    k_edges<<<((size_t)E * 32 + 255) / 256, 256>>>(x, ei, E);
    k_prep<<<(n + 255) / 256, 256>>>(batch, n);
    k_gemm<<<(n + 127) / 128, 256>>>(x, Wl, bl, Wr, batch, n);
    k_norm<<<1, 1024>>>(gw, gb, ms);
    k_out<<<(n * 32 + 255) / 256, 256>>>(x, batch, (float*)d_out, n);
}

// round 7
// speedup vs baseline: 1.0429x; 1.0429x over previous
#include <cuda_runtime.h>
#include <math.h>
#include <stdint.h>

#define NN 50000
#define DD 128
#define GG 8
#define EPSV 1e-5f

typedef unsigned long long ull;

// ---------------- scratch (static device globals; no allocation) ----------------
__device__ float g_agg[(size_t)NN * DD];   // neighbor sum -> mean (scaled in k_prep)
__device__ float g_f[(size_t)NN * DD];     // post-GELU features
__device__ float g_deg[NN];
__device__ float g_sumf[GG * DD];
__device__ float g_sumf2[GG * DD];
__device__ float g_cnt[GG];
__device__ float g_scaleA[GG * DD];
__device__ float g_shiftB[GG * DD];

// ---------------- K0: zero scratch ----------------
__global__ void k_zero() {
    int i = blockIdx.x * blockDim.x + threadIdx.x;
    if (i < NN * 32) ((float4*)g_agg)[i] = make_float4(0.f, 0.f, 0.f, 0.f);
    if (i < NN) g_deg[i] = 0.f;
    if (i < GG * DD) { g_sumf[i] = 0.f; g_sumf2[i] = 0.f; }
    if (i < GG) g_cnt[i] = 0.f;
}

// ---------------- K1: edge scatter (1 warp per edge, vector RED) ----------------
__global__ void k_edges(const float* __restrict__ x, const int* __restrict__ ei, int E) {
    int w = (blockIdx.x * blockDim.x + threadIdx.x) >> 5;
    int lane = threadIdx.x & 31;
    if (w >= E) return;
    int s = __ldg(&ei[w]);
    int d = __ldg(&ei[E + w]);
    float4 v = __ldg(&((const float4*)x)[(size_t)s * 32 + lane]);
    float* a = &g_agg[(size_t)d * DD + lane * 4];
    asm volatile("red.global.add.v4.f32 [%0], {%1,%2,%3,%4};"
                 :: "l"(a), "f"(v.x), "f"(v.y), "f"(v.z), "f"(v.w) : "memory");
    if (lane == 0) atomicAdd(&g_deg[d], 1.0f);
}

// ---------------- K2: scale agg -> mean (in place) + per-graph counts ----------------
// One warp per node; deg load is warp-uniform (broadcast).
__global__ void k_prep(const int* __restrict__ batch, int n) {
    __shared__ int hist[GG];
    if (threadIdx.x < GG) hist[threadIdx.x] = 0;
    __syncthreads();
    int i = blockIdx.x * blockDim.x + threadIdx.x;
    int w = i >> 5;
    int lane = i & 31;
    if (w < n) {
        float iv = 1.0f / fmaxf(g_deg[w], 1.0f);
        float4 v = ((const float4*)g_agg)[(size_t)w * 32 + lane];
        v.x *= iv; v.y *= iv; v.z *= iv; v.w *= iv;
        ((float4*)g_agg)[(size_t)w * 32 + lane] = v;
        if (lane == 0) atomicAdd(&hist[batch[w]], 1);
    }
    __syncthreads();
    if (threadIdx.x < GG && hist[threadIdx.x] > 0)
        atomicAdd(&g_cnt[threadIdx.x], (float)hist[threadIdx.x]);
}

// ---------------- K3: fused GEMM (K=256: [mean_agg | x] @ [Wl | Wr]^T)
// FFMA2 (fma.rn.f32x2) inner loop + full register prefetch of next chunk.
// __launch_bounds__(256,2) pins regs <= 128 so 2 CTAs/SM stay resident.
#define LDT 132

__global__ __launch_bounds__(256, 2) void k_gemm(
    const float* __restrict__ x, const float* __restrict__ Wl,
    const float* __restrict__ bl, const float* __restrict__ Wr,
    const int* __restrict__ batch, int n)
{
    __shared__ float sA[32 * LDT];
    __shared__ float sW[32 * LDT];

    const int tid = threadIdx.x;
    const int tx = tid & 15;          // col group: cols tx*8 .. tx*8+7
    const int ty = tid >> 4;          // row group: rows ty*8 .. ty*8+7
    const int row0 = blockIdx.x * 128;
    const int kv = tid & 7;           // float4 index within 32-k chunk
    const int rb = tid >> 3;          // 0..31

    // Packed accumulators: acc2[i][jp] = (C[i][2jp], C[i][2jp+1])
    ull acc2[8][4];
#pragma unroll
    for (int i = 0; i < 8; ++i)
#pragma unroll
        for (int jp = 0; jp < 4; ++jp) acc2[i][jp] = 0ULL;

    float4 pv[4], pw[4];   // prefetch registers

    auto load_chunk = [&](int kc) {
        const bool isA = (kc < 4);
        const int kq = (kc & 3) * 8;
        const float4* src  = isA ? (const float4*)g_agg : (const float4*)x;
        const float4* Wsrc = isA ? (const float4*)Wl : (const float4*)Wr;
#pragma unroll
        for (int p = 0; p < 4; ++p) {
            int r = rb + p * 32;
            int gr = row0 + r;
            pv[p] = (gr < n) ? __ldg(&src[(size_t)gr * 32 + kq + kv])
                             : make_float4(0.f, 0.f, 0.f, 0.f);
            pw[p] = __ldg(&Wsrc[(size_t)r * 32 + kq + kv]);
        }
    };

    load_chunk(0);

    for (int kc = 0; kc < 8; ++kc) {
        __syncthreads();
#pragma unroll
        for (int p = 0; p < 4; ++p) {
            int r = rb + p * 32;
            int kb = kv * 4;
            sA[(kb + 0) * LDT + r] = pv[p].x; sA[(kb + 1) * LDT + r] = pv[p].y;
            sA[(kb + 2) * LDT + r] = pv[p].z; sA[(kb + 3) * LDT + r] = pv[p].w;
            sW[(kb + 0) * LDT + r] = pw[p].x; sW[(kb + 1) * LDT + r] = pw[p].y;
            sW[(kb + 2) * LDT + r] = pw[p].z; sW[(kb + 3) * LDT + r] = pw[p].w;
        }
        __syncthreads();

        // prefetch next chunk while computing this one
        if (kc < 7) load_chunk(kc + 1);

#pragma unroll
        for (int k = 0; k < 32; ++k) {
            const float* pa = sA + k * LDT + ty * 8;
            const float* pwv = sW + k * LDT + tx * 8;
            float4 A0 = *(const float4*)(pa);      float4 A1 = *(const float4*)(pa + 4);
            float4 W0 = *(const float4*)(pwv);     float4 W1 = *(const float4*)(pwv + 4);
            float av[8] = {A0.x, A0.y, A0.z, A0.w, A1.x, A1.y, A1.z, A1.w};
            ull w2[4];
            asm("mov.b64 %0, {%1, %2};" : "=l"(w2[0]) : "f"(W0.x), "f"(W0.y));
            asm("mov.b64 %0, {%1, %2};" : "=l"(w2[1]) : "f"(W0.z), "f"(W0.w));
            asm("mov.b64 %0, {%1, %2};" : "=l"(w2[2]) : "f"(W1.x), "f"(W1.y));
            asm("mov.b64 %0, {%1, %2};" : "=l"(w2[3]) : "f"(W1.z), "f"(W1.w));
#pragma unroll
            for (int i = 0; i < 8; ++i) {
                ull a2;
                asm("mov.b64 %0, {%1, %1};" : "=l"(a2) : "f"(av[i]));
#pragma unroll
                for (int jp = 0; jp < 4; ++jp)
                    asm("fma.rn.f32x2 %0, %1, %2, %0;"
                        : "+l"(acc2[i][jp]) : "l"(a2), "l"(w2[jp]));
            }
        }
    }

    // ---- unpack accumulators ----
    float acc[8][8];
#pragma unroll
    for (int i = 0; i < 8; ++i)
#pragma unroll
        for (int jp = 0; jp < 4; ++jp) {
            float lo, hi;
            asm("mov.b64 {%0, %1}, %2;" : "=f"(lo), "=f"(hi) : "l"(acc2[i][jp]));
            acc[i][2 * jp] = lo; acc[i][2 * jp + 1] = hi;
        }

    // ---- epilogue: bias + exact GELU + store f + per-graph sum/sum2 ----
    float4 b0 = __ldg(&((const float4*)bl)[tx * 2]);
    float4 b1 = __ldg(&((const float4*)bl)[tx * 2 + 1]);
    float bb[8] = {b0.x, b0.y, b0.z, b0.w, b1.x, b1.y, b1.z, b1.w};

    float sf[8], sf2[8];
#pragma unroll
    for (int j = 0; j < 8; ++j) { sf[j] = 0.f; sf2[j] = 0.f; }
    int gprev = -1;

#pragma unroll
    for (int i = 0; i < 8; ++i) {
        int r = row0 + ty * 8 + i;
        if (r < n) {
            int g = batch[r];
            if (g != gprev) {
                if (gprev >= 0) {
#pragma unroll
                    for (int j = 0; j < 8; ++j) {
                        atomicAdd(&g_sumf[gprev * DD + tx * 8 + j], sf[j]);
                        atomicAdd(&g_sumf2[gprev * DD + tx * 8 + j], sf2[j]);
                        sf[j] = 0.f; sf2[j] = 0.f;
                    }
                }
                gprev = g;
            }
            float fv[8];
#pragma unroll
            for (int j = 0; j < 8; ++j) {
                float v = acc[i][j] + bb[j];
                v = 0.5f * v * (1.0f + erff(v * 0.70710678118654752f));
                fv[j] = v;
                sf[j] += v;
                sf2[j] += v * v;
            }
            float4 o0 = make_float4(fv[0], fv[1], fv[2], fv[3]);
            float4 o1 = make_float4(fv[4], fv[5], fv[6], fv[7]);
            ((float4*)g_f)[(size_t)r * 32 + tx * 2] = o0;
            ((float4*)g_f)[(size_t)r * 32 + tx * 2 + 1] = o1;
        }
    }
    if (gprev >= 0) {
#pragma unroll
        for (int j = 0; j < 8; ++j) {
            atomicAdd(&g_sumf[gprev * DD + tx * 8 + j], sf[j]);
            atomicAdd(&g_sumf2[gprev * DD + tx * 8 + j], sf2[j]);
        }
    }
}

// ---------------- K4: fold stats into per-(graph,col) scale/shift ----------------
__global__ void k_norm(const float* __restrict__ gw, const float* __restrict__ gb,
                       const float* __restrict__ ms) {
    int i = threadIdx.x;              // 1024 = G*D
    int c = i & 127;
    int g = i >> 7;
    float cnt = fmaxf(g_cnt[g], 1.0f);
    float m = g_sumf[i] / cnt;
    float e2 = g_sumf2[i] / cnt;
    float s = ms[c];
    float var = e2 - (2.0f * s - s * s) * m * m;   // E[(f - s*m)^2]
    var = fmaxf(var, 0.0f);
    float inv = rsqrtf(var + EPSV);
    float w = gw[c];
    g_scaleA[i] = inv * w;
    g_shiftB[i] = gb[c] - s * m * inv * w;
}

// ---------------- K5: out = f*scaleA + shiftB + x ----------------
__global__ void k_out(const float* __restrict__ x, const int* __restrict__ batch,
                      float* __restrict__ out, int n) {
    int i = blockIdx.x * blockDim.x + threadIdx.x;
    if (i >= n * 32) return;
    int row = i >> 5;
    int c4 = i & 31;
    int g = batch[row];                       // uniform per warp (1 warp == 1 row)
    float4 f = ((const float4*)g_f)[i];
    float4 s = __ldg(&((const float4*)g_scaleA)[g * 32 + c4]);
    float4 b = __ldg(&((const float4*)g_shiftB)[g * 32 + c4]);
    float4 xv = ((const float4*)x)[i];
    float4 o;
    o.x = fmaf(f.x, s.x, b.x) + xv.x;
    o.y = fmaf(f.y, s.y, b.y) + xv.y;
    o.z = fmaf(f.z, s.z, b.z) + xv.z;
    o.w = fmaf(f.w, s.w, b.w) + xv.w;
    ((float4*)out)[i] = o;
}

// ---------------- host launcher ----------------
extern "C" void kernel_launch(void* const* d_in, const int* in_sizes, int n_in,
                              void* d_out, int out_size) {
    const float* x     = (const float*)d_in[0];
    const int*   ei    = (const int*)d_in[1];
    const int*   batch = (const int*)d_in[2];
    // d_in[3] = num_graphs (fixed G=8)
    const float* Wl = (const float*)d_in[4];
    const float* bl = (const float*)d_in[5];
    const float* Wr = (const float*)d_in[6];
    const float* gw = (const float*)d_in[7];
    const float* gb = (const float*)d_in[8];
    const float* ms = (const float*)d_in[9];

    int n = in_sizes[0] / DD;
    int E = in_sizes[1] / 2;

    k_zero<<<(NN * 32 + 255) / 256, 256>>>();
    k_edges<<<((size_t)E * 32 + 255) / 256, 256>>>(x, ei, E);
    k_prep<<<((size_t)n * 32 + 255) / 256, 256>>>(batch, n);
    k_gemm<<<(n + 127) / 128, 256>>>(x, Wl, bl, Wr, batch, n);
    k_norm<<<1, 1024>>>(gw, gb, ms);
    k_out<<<(n * 32 + 255) / 256, 256>>>(x, batch, (float*)d_out, n);
}

// round 9
// speedup vs baseline: 1.9520x; 1.8718x over previous
#include <cuda_runtime.h>
#include <cuda_bf16.h>
#include <math.h>
#include <stdint.h>

#define NN 50000
#define DD 128
#define GG 8
#define EPSV 1e-5f

typedef unsigned long long ull;

// ---------------- scratch ----------------
__device__ float g_agg[(size_t)NN * DD];
__device__ float g_f[(size_t)NN * DD];
__device__ float g_deg[NN];
__device__ float g_sumf[GG * DD];
__device__ float g_sumf2[GG * DD];
__device__ float g_cnt[GG];
__device__ float g_scaleA[GG * DD];
__device__ float g_shiftB[GG * DD];

// ---------------- K0: zero ----------------
__global__ void k_zero() {
    int i = blockIdx.x * blockDim.x + threadIdx.x;
    if (i < NN * 32) ((float4*)g_agg)[i] = make_float4(0.f, 0.f, 0.f, 0.f);
    if (i < NN) g_deg[i] = 0.f;
    if (i < GG * DD) { g_sumf[i] = 0.f; g_sumf2[i] = 0.f; }
    if (i < GG) g_cnt[i] = 0.f;
}

// ---------------- K1: edge scatter (1 warp per edge, vector RED) ----------------
__global__ void k_edges(const float* __restrict__ x, const int* __restrict__ ei, int E) {
    int w = (blockIdx.x * blockDim.x + threadIdx.x) >> 5;
    int lane = threadIdx.x & 31;
    if (w >= E) return;
    int s = __ldg(&ei[w]);
    int d = __ldg(&ei[E + w]);
    float4 v = __ldg(&((const float4*)x)[(size_t)s * 32 + lane]);
    float* a = &g_agg[(size_t)d * DD + lane * 4];
    asm volatile("red.global.add.v4.f32 [%0], {%1,%2,%3,%4};"
                 :: "l"(a), "f"(v.x), "f"(v.y), "f"(v.z), "f"(v.w) : "memory");
    if (lane == 0) atomicAdd(&g_deg[d], 1.0f);
}

// ---------------- K2: per-graph node counts ----------------
__global__ void k_prep(const int* __restrict__ batch, int n) {
    __shared__ int hist[GG];
    if (threadIdx.x < GG) hist[threadIdx.x] = 0;
    __syncthreads();
    int i = blockIdx.x * blockDim.x + threadIdx.x;
    if (i < n) atomicAdd(&hist[batch[i]], 1);
    __syncthreads();
    if (threadIdx.x < GG && hist[threadIdx.x] > 0)
        atomicAdd(&g_cnt[threadIdx.x], (float)hist[threadIdx.x]);
}

// ---------------- K3: mma.sync bf16-split GEMM + GELU + per-graph sums ----------------
// C[128,128] = [agg/deg | x][128,256] @ [Wl | Wr]^T, 3-term bf16 hi/lo split.
// 512 threads = 16 warps in 4m x 4n; warp tile 32x32 via m16n8k16 (mi2 x ni4).
// K staged in 8 chunks of 32. Tiles [128][40] bf16 (80B rows): slot=(5r+g)%8,
// gcd(5,8)=1 -> 8 consecutive rows hit distinct 16B slots: conflict-free ldmatrix.
#define TPITCH 80
#define TSIZE  (128 * TPITCH)

#define LDM4(r, a) \
    asm volatile("ldmatrix.sync.aligned.m8n8.x4.shared.b16 {%0,%1,%2,%3}, [%4];" \
                 : "=r"((r)[0]), "=r"((r)[1]), "=r"((r)[2]), "=r"((r)[3]) : "r"(a))

#define MMA(c, A, b0, b1) \
    asm volatile("mma.sync.aligned.m16n8k16.row.col.f32.bf16.bf16.f32 " \
                 "{%0,%1,%2,%3},{%4,%5,%6,%7},{%8,%9},{%0,%1,%2,%3};" \
                 : "+f"((c)[0]), "+f"((c)[1]), "+f"((c)[2]), "+f"((c)[3]) \
                 : "r"((A)[0]), "r"((A)[1]), "r"((A)[2]), "r"((A)[3]), "r"(b0), "r"(b1))

__device__ __forceinline__ void cvt_store8(char* hi, char* lo, uint32_t off,
                                           float4 u, float4 v) {
    float f[8] = {u.x, u.y, u.z, u.w, v.x, v.y, v.z, v.w};
    uint32_t H[4], L[4];
#pragma unroll
    for (int i = 0; i < 4; ++i) {
        __nv_bfloat16 h0 = __float2bfloat16(f[2 * i]);
        __nv_bfloat16 h1 = __float2bfloat16(f[2 * i + 1]);
        float r0 = f[2 * i] - __bfloat162float(h0);
        float r1 = f[2 * i + 1] - __bfloat162float(h1);
        __nv_bfloat16 l0 = __float2bfloat16(r0);
        __nv_bfloat16 l1 = __float2bfloat16(r1);
        __nv_bfloat162 hh(h0, h1), ll(l0, l1);
        H[i] = *(uint32_t*)&hh;
        L[i] = *(uint32_t*)&ll;
    }
    *(uint4*)(hi + off) = make_uint4(H[0], H[1], H[2], H[3]);
    *(uint4*)(lo + off) = make_uint4(L[0], L[1], L[2], L[3]);
}

__global__ __launch_bounds__(512) void k_mma(
    const float* __restrict__ x, const float* __restrict__ Wl,
    const float* __restrict__ bl, const float* __restrict__ Wr,
    const int* __restrict__ batch, int n)
{
    __shared__ __align__(16) char sm[4 * TSIZE];   // Ahi | Alo | Bhi | Blo = 40KB
    char* sAhi = sm;
    char* sAlo = sm + TSIZE;
    char* sBhi = sm + 2 * TSIZE;
    char* sBlo = sm + 3 * TSIZE;

    const int tid = threadIdx.x;
    const int wid = tid >> 5;
    const int lane = tid & 31;
    const int wm = wid >> 2;          // 0..3 -> rows wm*32..+31
    const int wn = wid & 3;           // 0..3 -> cols wn*32..+31
    const int row0 = blockIdx.x * 128;

    // staging role: one 16B granule (8 k-consecutive bf16) per matrix per chunk
    const int srow = tid >> 2;        // 0..127
    const int sgc = tid & 3;          // granule col 0..3
    const uint32_t soff = srow * TPITCH + sgc * 16;

    float acc[2][4][4];
#pragma unroll
    for (int mi = 0; mi < 2; ++mi)
#pragma unroll
        for (int ni = 0; ni < 4; ++ni)
#pragma unroll
            for (int t = 0; t < 4; ++t) acc[mi][ni][t] = 0.f;

    float4 pa[2], pb[2];
    auto load_chunk = [&](int c) {
        const float4* As = (c < 4) ? (const float4*)g_agg : (const float4*)x;
        const float4* Bs = (c < 4) ? (const float4*)Wl : (const float4*)Wr;
        int fq = (c & 3) * 8 + sgc * 2;
        int gr = row0 + srow;
        if (gr < n) {
            pa[0] = __ldg(&As[(size_t)gr * 32 + fq]);
            pa[1] = __ldg(&As[(size_t)gr * 32 + fq + 1]);
            if (c < 4) {
                float iv = 1.0f / fmaxf(g_deg[gr], 1.0f);
                pa[0].x *= iv; pa[0].y *= iv; pa[0].z *= iv; pa[0].w *= iv;
                pa[1].x *= iv; pa[1].y *= iv; pa[1].z *= iv; pa[1].w *= iv;
            }
        } else {
            pa[0] = make_float4(0.f, 0.f, 0.f, 0.f);
            pa[1] = pa[0];
        }
        pb[0] = __ldg(&Bs[(size_t)srow * 32 + fq]);
        pb[1] = __ldg(&Bs[(size_t)srow * 32 + fq + 1]);
    };

    // per-thread ldmatrix base addresses (bytes into tile)
    // A frag order (m16k16): (m0-7,k0-7)(m8-15,k0-7)(m0-7,k8-15)(m8-15,k8-15)
    const uint32_t a_base =
        (uint32_t)((wm * 32 + (lane & 7) + ((lane >> 3) & 1) * 8) * TPITCH
                   + (lane >> 4) * 16);
    // B frag order (n16k16): (n0-7,k0-7)(n0-7,k8-15)(n8-15,k0-7)(n8-15,k8-15)
    const uint32_t b_base =
        (uint32_t)((wn * 32 + (lane & 7) + (lane >> 4) * 8) * TPITCH
                   + ((lane >> 3) & 1) * 16);

    uint32_t smb = (uint32_t)__cvta_generic_to_shared(sm);
    uint32_t aAhi = smb + a_base;
    uint32_t aAlo = smb + TSIZE + a_base;
    uint32_t aBhi = smb + 2 * TSIZE + b_base;
    uint32_t aBlo = smb + 3 * TSIZE + b_base;

    load_chunk(0);

    for (int c = 0; c < 8; ++c) {
        __syncthreads();
        cvt_store8(sAhi, sAlo, soff, pa[0], pa[1]);
        cvt_store8(sBhi, sBlo, soff, pb[0], pb[1]);
        __syncthreads();
        if (c < 7) load_chunk(c + 1);

#pragma unroll
        for (int s = 0; s < 2; ++s) {
            uint32_t Ah[2][4], Al[2][4], Bh[2][4], Bl[2][4];
            LDM4(Ah[0], aAhi + s * 32);
            LDM4(Ah[1], aAhi + 16 * TPITCH + s * 32);
            LDM4(Al[0], aAlo + s * 32);
            LDM4(Al[1], aAlo + 16 * TPITCH + s * 32);
            LDM4(Bh[0], aBhi + s * 32);
            LDM4(Bh[1], aBhi + 16 * TPITCH + s * 32);
            LDM4(Bl[0], aBlo + s * 32);
            LDM4(Bl[1], aBlo + 16 * TPITCH + s * 32);
#pragma unroll
            for (int mi = 0; mi < 2; ++mi)
#pragma unroll
                for (int ni = 0; ni < 4; ++ni) {
                    uint32_t b0h = Bh[ni >> 1][(ni & 1) * 2];
                    uint32_t b1h = Bh[ni >> 1][(ni & 1) * 2 + 1];
                    uint32_t b0l = Bl[ni >> 1][(ni & 1) * 2];
                    uint32_t b1l = Bl[ni >> 1][(ni & 1) * 2 + 1];
                    MMA(acc[mi][ni], Ah[mi], b0h, b1h);
                    MMA(acc[mi][ni], Ah[mi], b0l, b1l);
                    MMA(acc[mi][ni], Al[mi], b0h, b1h);
                }
        }
    }

    // ---- epilogue ----
    const int qr = lane >> 2;         // 0..7
    const int qc = lane & 3;          // 0..3
    const int rl = row0 + wm * 32;    // warp strip base row

    int g0 = -1;
    if (rl < n) g0 = __ldg(&batch[rl]);
    bool uniform = ((rl + 31) < n) && (__ldg(&batch[rl + 31]) == g0);

    float2 bias[4];
#pragma unroll
    for (int ni = 0; ni < 4; ++ni)
        bias[ni] = *(const float2*)&bl[wn * 32 + ni * 8 + 2 * qc];

    float sf[4][2], sq[4][2];
#pragma unroll
    for (int ni = 0; ni < 4; ++ni) { sf[ni][0] = sf[ni][1] = 0.f; sq[ni][0] = sq[ni][1] = 0.f; }

#pragma unroll
    for (int j = 0; j < 4; ++j) {
        int row = rl + qr + j * 8;
        bool v = row < n;
        int mi = j >> 1, h = j & 1;
        float fv[4][2];
#pragma unroll
        for (int ni = 0; ni < 4; ++ni) {
#pragma unroll
            for (int t = 0; t < 2; ++t) {
                float b = t ? bias[ni].y : bias[ni].x;
                float val = acc[mi][ni][h * 2 + t] + b;
                fv[ni][t] = 0.5f * val * (1.0f + erff(val * 0.70710678118654752f));
            }
        }
        if (v) {
#pragma unroll
            for (int ni = 0; ni < 4; ++ni)
                *(float2*)&g_f[(size_t)row * DD + wn * 32 + ni * 8 + 2 * qc] =
                    make_float2(fv[ni][0], fv[ni][1]);
        }
        if (uniform) {
#pragma unroll
            for (int ni = 0; ni < 4; ++ni)
#pragma unroll
                for (int t = 0; t < 2; ++t) {
                    sf[ni][t] += fv[ni][t];
                    sq[ni][t] += fv[ni][t] * fv[ni][t];
                }
        } else if (v) {
            int g = __ldg(&batch[row]);
#pragma unroll
            for (int ni = 0; ni < 4; ++ni)
#pragma unroll
                for (int t = 0; t < 2; ++t) {
                    atomicAdd(&g_sumf[g * DD + wn * 32 + ni * 8 + 2 * qc + t], fv[ni][t]);
                    atomicAdd(&g_sumf2[g * DD + wn * 32 + ni * 8 + 2 * qc + t],
                              fv[ni][t] * fv[ni][t]);
                }
        }
    }

    if (uniform) {
        // butterfly over qr (masks 4,8,16); qc preserved
#pragma unroll
        for (int mask = 4; mask <= 16; mask <<= 1) {
#pragma unroll
            for (int ni = 0; ni < 4; ++ni)
#pragma unroll
                for (int t = 0; t < 2; ++t) {
                    sf[ni][t] += __shfl_xor_sync(0xffffffff, sf[ni][t], mask);
                    sq[ni][t] += __shfl_xor_sync(0xffffffff, sq[ni][t], mask);
                }
        }
        if (qr == 0) {
#pragma unroll
            for (int ni = 0; ni < 4; ++ni)
#pragma unroll
                for (int t = 0; t < 2; ++t) {
                    atomicAdd(&g_sumf[g0 * DD + wn * 32 + ni * 8 + 2 * qc + t], sf[ni][t]);
                    atomicAdd(&g_sumf2[g0 * DD + wn * 32 + ni * 8 + 2 * qc + t], sq[ni][t]);
                }
        }
    }
}

// ---------------- K4: fold stats ----------------
__global__ void k_norm(const float* __restrict__ gw, const float* __restrict__ gb,
                       const float* __restrict__ ms) {
    int i = threadIdx.x;
    int c = i & 127;
    int g = i >> 7;
    float cnt = fmaxf(g_cnt[g], 1.0f);
    float m = g_sumf[i] / cnt;
    float e2 = g_sumf2[i] / cnt;
    float s = ms[c];
    float var = e2 - (2.0f * s - s * s) * m * m;
    var = fmaxf(var, 0.0f);
    float inv = rsqrtf(var + EPSV);
    float w = gw[c];
    g_scaleA[i] = inv * w;
    g_shiftB[i] = gb[c] - s * m * inv * w;
}

// ---------------- K5: out = f*scaleA + shiftB + x ----------------
__global__ void k_out(const float* __restrict__ x, const int* __restrict__ batch,
                      float* __restrict__ out, int n) {
    int i = blockIdx.x * blockDim.x + threadIdx.x;
    if (i >= n * 32) return;
    int row = i >> 5;
    int c4 = i & 31;
    int g = batch[row];
    float4 f = ((const float4*)g_f)[i];
    float4 s = __ldg(&((const float4*)g_scaleA)[g * 32 + c4]);
    float4 b = __ldg(&((const float4*)g_shiftB)[g * 32 + c4]);
    float4 xv = ((const float4*)x)[i];
    float4 o;
    o.x = fmaf(f.x, s.x, b.x) + xv.x;
    o.y = fmaf(f.y, s.y, b.y) + xv.y;
    o.z = fmaf(f.z, s.z, b.z) + xv.z;
    o.w = fmaf(f.w, s.w, b.w) + xv.w;
    ((float4*)out)[i] = o;
}

// ---------------- host launcher ----------------
extern "C" void kernel_launch(void* const* d_in, const int* in_sizes, int n_in,
                              void* d_out, int out_size) {
    const float* x     = (const float*)d_in[0];
    const int*   ei    = (const int*)d_in[1];
    const int*   batch = (const int*)d_in[2];
    const float* Wl = (const float*)d_in[4];
    const float* bl = (const float*)d_in[5];
    const float* Wr = (const float*)d_in[6];
    const float* gw = (const float*)d_in[7];
    const float* gb = (const float*)d_in[8];
    const float* ms = (const float*)d_in[9];

    int n = in_sizes[0] / DD;
    int E = in_sizes[1] / 2;

    k_zero<<<(NN * 32 + 255) / 256, 256>>>();
    k_edges<<<((size_t)E * 32 + 255) / 256, 256>>>(x, ei, E);
    k_prep<<<(n + 255) / 256, 256>>>(batch, n);
    k_mma<<<(n + 127) / 128, 512>>>(x, Wl, bl, Wr, batch, n);
    k_norm<<<1, 1024>>>(gw, gb, ms);
    k_out<<<(n * 32 + 255) / 256, 256>>>(x, batch, (float*)d_out, n);
}

// round 10
// speedup vs baseline: 2.6493x; 1.3572x over previous
#include <cuda_runtime.h>
#include <cuda_bf16.h>
#include <math.h>
#include <stdint.h>

#define NN 50000
#define EE 600000
#define DD 128
#define GG 8
#define EPSV 1e-5f

typedef unsigned long long ull;

// ---------------- scratch ----------------
__device__ float g_agg[(size_t)NN * DD];   // mean-aggregated neighbor features
__device__ float g_f[(size_t)NN * DD];
__device__ int   g_degi[NN];
__device__ int   g_rowptr[NN];
__device__ int   g_pos[NN];
__device__ int   g_srcs[EE];
__device__ int   g_bsum[256];
__device__ float g_sumf[GG * DD];
__device__ float g_sumf2[GG * DD];
__device__ float g_cnt[GG];
__device__ float g_scaleA[GG * DD];
__device__ float g_shiftB[GG * DD];

__device__ __forceinline__ int wscan_incl(int v, int lane) {
#pragma unroll
    for (int o = 1; o < 32; o <<= 1) {
        int t = __shfl_up_sync(0xffffffff, v, o);
        if (lane >= o) v += t;
    }
    return v;
}

// ---------------- K0: zero counters/stats ----------------
__global__ void k_zero() {
    int i = blockIdx.x * blockDim.x + threadIdx.x;
    if (i < NN) { g_degi[i] = 0; g_pos[i] = 0; }
    if (i < GG * DD) { g_sumf[i] = 0.f; g_sumf2[i] = 0.f; }
    if (i < GG) g_cnt[i] = 0.f;
}

// ---------------- K1: degree histogram ----------------
__global__ void k_hist(const int* __restrict__ ei, int E) {
    int i = blockIdx.x * blockDim.x + threadIdx.x;
    if (i < E) atomicAdd(&g_degi[__ldg(&ei[E + i])], 1);
}

// ---------------- K2a: block-level exclusive scan of deg + graph node counts ----------------
__global__ void k_scan1(const int* __restrict__ batch, int n) {
    __shared__ int wsum[8];
    __shared__ int hist[GG];
    int tid = threadIdx.x, lane = tid & 31, wd = tid >> 5;
    if (tid < GG) hist[tid] = 0;
    __syncthreads();
    int i = blockIdx.x * 256 + tid;
    int v = (i < n) ? g_degi[i] : 0;
    if (i < n) atomicAdd(&hist[__ldg(&batch[i])], 1);
    int inc = wscan_incl(v, lane);
    if (lane == 31) wsum[wd] = inc;
    __syncthreads();
    if (wd == 0) {
        int s = (lane < 8) ? wsum[lane] : 0;
        int si = wscan_incl(s, lane);
        if (lane < 8) wsum[lane] = si - s;
    }
    __syncthreads();
    int excl = inc - v + wsum[wd];
    if (i < n) g_rowptr[i] = excl;
    if (tid == 255) g_bsum[blockIdx.x] = excl + v;
    if (tid < GG && hist[tid] > 0) atomicAdd(&g_cnt[tid], (float)hist[tid]);
}

// ---------------- K2b: scan the 196 block sums ----------------
__global__ void k_scan2(int nb) {
    __shared__ int wsum[8];
    int tid = threadIdx.x, lane = tid & 31, wd = tid >> 5;
    int v = (tid < nb) ? g_bsum[tid] : 0;
    int inc = wscan_incl(v, lane);
    if (lane == 31) wsum[wd] = inc;
    __syncthreads();
    if (wd == 0) {
        int s = (lane < 8) ? wsum[lane] : 0;
        int si = wscan_incl(s, lane);
        if (lane < 8) wsum[lane] = si - s;
    }
    __syncthreads();
    if (tid < nb) g_bsum[tid] = inc - v + wsum[wd];
}

// ---------------- K2c: add block offsets ----------------
__global__ void k_scan3(int n) {
    int i = blockIdx.x * blockDim.x + threadIdx.x;
    if (i < n) g_rowptr[i] += g_bsum[i >> 8];
}

// ---------------- K3: fill CSR source lists ----------------
__global__ void k_fill(const int* __restrict__ ei, int E) {
    int e = blockIdx.x * blockDim.x + threadIdx.x;
    if (e >= E) return;
    int s = __ldg(&ei[e]);
    int d = __ldg(&ei[E + e]);
    int p = atomicAdd(&g_pos[d], 1);
    g_srcs[g_rowptr[d] + p] = s;
}

// ---------------- K4: gather-aggregate (1 warp/node) -> mean ----------------
__global__ void k_gather(const float* __restrict__ x, int n) {
    int gt = blockIdx.x * blockDim.x + threadIdx.x;
    int w = gt >> 5, lane = gt & 31;
    if (w >= n) return;
    int start = g_rowptr[w];
    int deg = g_degi[w];
    float4 acc = make_float4(0.f, 0.f, 0.f, 0.f);
    int j = 0;
    // unroll by 2 with src prefetch to break the src->x dependency chain
    for (; j + 2 <= deg; j += 2) {
        int s0 = __ldg(&g_srcs[start + j]);
        int s1 = __ldg(&g_srcs[start + j + 1]);
        float4 v0 = __ldg(&((const float4*)x)[(size_t)s0 * 32 + lane]);
        float4 v1 = __ldg(&((const float4*)x)[(size_t)s1 * 32 + lane]);
        acc.x += v0.x + v1.x; acc.y += v0.y + v1.y;
        acc.z += v0.z + v1.z; acc.w += v0.w + v1.w;
    }
    if (j < deg) {
        int s0 = __ldg(&g_srcs[start + j]);
        float4 v0 = __ldg(&((const float4*)x)[(size_t)s0 * 32 + lane]);
        acc.x += v0.x; acc.y += v0.y; acc.z += v0.z; acc.w += v0.w;
    }
    float iv = 1.0f / fmaxf((float)deg, 1.0f);
    acc.x *= iv; acc.y *= iv; acc.z *= iv; acc.w *= iv;
    ((float4*)g_agg)[(size_t)w * 32 + lane] = acc;
}

// ---------------- K5: mma.sync bf16-split GEMM + GELU + per-graph sums ----------------
#define TPITCH 80
#define TSIZE  (128 * TPITCH)

#define LDM4(r, a) \
    asm volatile("ldmatrix.sync.aligned.m8n8.x4.shared.b16 {%0,%1,%2,%3}, [%4];" \
                 : "=r"((r)[0]), "=r"((r)[1]), "=r"((r)[2]), "=r"((r)[3]) : "r"(a))

#define MMA(c, A, b0, b1) \
    asm volatile("mma.sync.aligned.m16n8k16.row.col.f32.bf16.bf16.f32 " \
                 "{%0,%1,%2,%3},{%4,%5,%6,%7},{%8,%9},{%0,%1,%2,%3};" \
                 : "+f"((c)[0]), "+f"((c)[1]), "+f"((c)[2]), "+f"((c)[3]) \
                 : "r"((A)[0]), "r"((A)[1]), "r"((A)[2]), "r"((A)[3]), "r"(b0), "r"(b1))

__device__ __forceinline__ void cvt_store8(char* hi, char* lo, uint32_t off,
                                           float4 u, float4 v) {
    float f[8] = {u.x, u.y, u.z, u.w, v.x, v.y, v.z, v.w};
    uint32_t H[4], L[4];
#pragma unroll
    for (int i = 0; i < 4; ++i) {
        __nv_bfloat16 h0 = __float2bfloat16(f[2 * i]);
        __nv_bfloat16 h1 = __float2bfloat16(f[2 * i + 1]);
        float r0 = f[2 * i] - __bfloat162float(h0);
        float r1 = f[2 * i + 1] - __bfloat162float(h1);
        __nv_bfloat16 l0 = __float2bfloat16(r0);
        __nv_bfloat16 l1 = __float2bfloat16(r1);
        __nv_bfloat162 hh(h0, h1), ll(l0, l1);
        H[i] = *(uint32_t*)&hh;
        L[i] = *(uint32_t*)&ll;
    }
    *(uint4*)(hi + off) = make_uint4(H[0], H[1], H[2], H[3]);
    *(uint4*)(lo + off) = make_uint4(L[0], L[1], L[2], L[3]);
}

__global__ __launch_bounds__(512) void k_mma(
    const float* __restrict__ x, const float* __restrict__ Wl,
    const float* __restrict__ bl, const float* __restrict__ Wr,
    const int* __restrict__ batch, int n)
{
    __shared__ __align__(16) char sm[4 * TSIZE];   // Ahi | Alo | Bhi | Blo = 40KB
    char* sAhi = sm;
    char* sAlo = sm + TSIZE;
    char* sBhi = sm + 2 * TSIZE;
    char* sBlo = sm + 3 * TSIZE;

    const int tid = threadIdx.x;
    const int wid = tid >> 5;
    const int lane = tid & 31;
    const int wm = wid >> 2;
    const int wn = wid & 3;
    const int row0 = blockIdx.x * 128;

    const int srow = tid >> 2;
    const int sgc = tid & 3;
    const uint32_t soff = srow * TPITCH + sgc * 16;

    float acc[2][4][4];
#pragma unroll
    for (int mi = 0; mi < 2; ++mi)
#pragma unroll
        for (int ni = 0; ni < 4; ++ni)
#pragma unroll
            for (int t = 0; t < 4; ++t) acc[mi][ni][t] = 0.f;

    float4 pa[2], pb[2];
    auto load_chunk = [&](int c) {
        const float4* As = (c < 4) ? (const float4*)g_agg : (const float4*)x;
        const float4* Bs = (c < 4) ? (const float4*)Wl : (const float4*)Wr;
        int fq = (c & 3) * 8 + sgc * 2;
        int gr = row0 + srow;
        if (gr < n) {
            pa[0] = __ldg(&As[(size_t)gr * 32 + fq]);
            pa[1] = __ldg(&As[(size_t)gr * 32 + fq + 1]);
        } else {
            pa[0] = make_float4(0.f, 0.f, 0.f, 0.f);
            pa[1] = pa[0];
        }
        pb[0] = __ldg(&Bs[(size_t)srow * 32 + fq]);
        pb[1] = __ldg(&Bs[(size_t)srow * 32 + fq + 1]);
    };

    const uint32_t a_base =
        (uint32_t)((wm * 32 + (lane & 7) + ((lane >> 3) & 1) * 8) * TPITCH
                   + (lane >> 4) * 16);
    const uint32_t b_base =
        (uint32_t)((wn * 32 + (lane & 7) + (lane >> 4) * 8) * TPITCH
                   + ((lane >> 3) & 1) * 16);

    uint32_t smb = (uint32_t)__cvta_generic_to_shared(sm);
    uint32_t aAhi = smb + a_base;
    uint32_t aAlo = smb + TSIZE + a_base;
    uint32_t aBhi = smb + 2 * TSIZE + b_base;
    uint32_t aBlo = smb + 3 * TSIZE + b_base;

    load_chunk(0);

    for (int c = 0; c < 8; ++c) {
        __syncthreads();
        cvt_store8(sAhi, sAlo, soff, pa[0], pa[1]);
        cvt_store8(sBhi, sBlo, soff, pb[0], pb[1]);
        __syncthreads();
        if (c < 7) load_chunk(c + 1);

#pragma unroll
        for (int s = 0; s < 2; ++s) {
            uint32_t Ah[2][4], Al[2][4], Bh[2][4], Bl[2][4];
            LDM4(Ah[0], aAhi + s * 32);
            LDM4(Ah[1], aAhi + 16 * TPITCH + s * 32);
            LDM4(Al[0], aAlo + s * 32);
            LDM4(Al[1], aAlo + 16 * TPITCH + s * 32);
            LDM4(Bh[0], aBhi + s * 32);
            LDM4(Bh[1], aBhi + 16 * TPITCH + s * 32);
            LDM4(Bl[0], aBlo + s * 32);
            LDM4(Bl[1], aBlo + 16 * TPITCH + s * 32);
#pragma unroll
            for (int mi = 0; mi < 2; ++mi)
#pragma unroll
                for (int ni = 0; ni < 4; ++ni) {
                    uint32_t b0h = Bh[ni >> 1][(ni & 1) * 2];
                    uint32_t b1h = Bh[ni >> 1][(ni & 1) * 2 + 1];
                    uint32_t b0l = Bl[ni >> 1][(ni & 1) * 2];
                    uint32_t b1l = Bl[ni >> 1][(ni & 1) * 2 + 1];
                    MMA(acc[mi][ni], Ah[mi], b0h, b1h);
                    MMA(acc[mi][ni], Ah[mi], b0l, b1l);
                    MMA(acc[mi][ni], Al[mi], b0h, b1h);
                }
        }
    }

    // ---- epilogue ----
    const int qr = lane >> 2;
    const int qc = lane & 3;
    const int rl = row0 + wm * 32;

    int g0 = -1;
    if (rl < n) g0 = __ldg(&batch[rl]);
    bool uniform = ((rl + 31) < n) && (__ldg(&batch[rl + 31]) == g0);

    float2 bias[4];
#pragma unroll
    for (int ni = 0; ni < 4; ++ni)
        bias[ni] = *(const float2*)&bl[wn * 32 + ni * 8 + 2 * qc];

    float sf[4][2], sq[4][2];
#pragma unroll
    for (int ni = 0; ni < 4; ++ni) { sf[ni][0] = sf[ni][1] = 0.f; sq[ni][0] = sq[ni][1] = 0.f; }

#pragma unroll
    for (int j = 0; j < 4; ++j) {
        int row = rl + qr + j * 8;
        bool v = row < n;
        int mi = j >> 1, h = j & 1;
        float fv[4][2];
#pragma unroll
        for (int ni = 0; ni < 4; ++ni) {
#pragma unroll
            for (int t = 0; t < 2; ++t) {
                float b = t ? bias[ni].y : bias[ni].x;
                float val = acc[mi][ni][h * 2 + t] + b;
                fv[ni][t] = 0.5f * val * (1.0f + erff(val * 0.70710678118654752f));
            }
        }
        if (v) {
#pragma unroll
            for (int ni = 0; ni < 4; ++ni)
                *(float2*)&g_f[(size_t)row * DD + wn * 32 + ni * 8 + 2 * qc] =
                    make_float2(fv[ni][0], fv[ni][1]);
        }
        if (uniform) {
#pragma unroll
            for (int ni = 0; ni < 4; ++ni)
#pragma unroll
                for (int t = 0; t < 2; ++t) {
                    sf[ni][t] += fv[ni][t];
                    sq[ni][t] += fv[ni][t] * fv[ni][t];
                }
        } else if (v) {
            int g = __ldg(&batch[row]);
#pragma unroll
            for (int ni = 0; ni < 4; ++ni)
#pragma unroll
                for (int t = 0; t < 2; ++t) {
                    atomicAdd(&g_sumf[g * DD + wn * 32 + ni * 8 + 2 * qc + t], fv[ni][t]);
                    atomicAdd(&g_sumf2[g * DD + wn * 32 + ni * 8 + 2 * qc + t],
                              fv[ni][t] * fv[ni][t]);
                }
        }
    }

    if (uniform) {
#pragma unroll
        for (int mask = 4; mask <= 16; mask <<= 1) {
#pragma unroll
            for (int ni = 0; ni < 4; ++ni)
#pragma unroll
                for (int t = 0; t < 2; ++t) {
                    sf[ni][t] += __shfl_xor_sync(0xffffffff, sf[ni][t], mask);
                    sq[ni][t] += __shfl_xor_sync(0xffffffff, sq[ni][t], mask);
                }
        }
        if (qr == 0) {
#pragma unroll
            for (int ni = 0; ni < 4; ++ni)
#pragma unroll
                for (int t = 0; t < 2; ++t) {
                    atomicAdd(&g_sumf[g0 * DD + wn * 32 + ni * 8 + 2 * qc + t], sf[ni][t]);
                    atomicAdd(&g_sumf2[g0 * DD + wn * 32 + ni * 8 + 2 * qc + t], sq[ni][t]);
                }
        }
    }
}

// ---------------- K6: fold stats ----------------
__global__ void k_norm(const float* __restrict__ gw, const float* __restrict__ gb,
                       const float* __restrict__ ms) {
    int i = threadIdx.x;
    int c = i & 127;
    int g = i >> 7;
    float cnt = fmaxf(g_cnt[g], 1.0f);
    float m = g_sumf[i] / cnt;
    float e2 = g_sumf2[i] / cnt;
    float s = ms[c];
    float var = e2 - (2.0f * s - s * s) * m * m;
    var = fmaxf(var, 0.0f);
    float inv = rsqrtf(var + EPSV);
    float w = gw[c];
    g_scaleA[i] = inv * w;
    g_shiftB[i] = gb[c] - s * m * inv * w;
}

// ---------------- K7: out = f*scaleA + shiftB + x ----------------
__global__ void k_out(const float* __restrict__ x, const int* __restrict__ batch,
                      float* __restrict__ out, int n) {
    int i = blockIdx.x * blockDim.x + threadIdx.x;
    if (i >= n * 32) return;
    int row = i >> 5;
    int c4 = i & 31;
    int g = batch[row];
    float4 f = ((const float4*)g_f)[i];
    float4 s = __ldg(&((const float4*)g_scaleA)[g * 32 + c4]);
    float4 b = __ldg(&((const float4*)g_shiftB)[g * 32 + c4]);
    float4 xv = ((const float4*)x)[i];
    float4 o;
    o.x = fmaf(f.x, s.x, b.x) + xv.x;
    o.y = fmaf(f.y, s.y, b.y) + xv.y;
    o.z = fmaf(f.z, s.z, b.z) + xv.z;
    o.w = fmaf(f.w, s.w, b.w) + xv.w;
    ((float4*)out)[i] = o;
}

// ---------------- host launcher ----------------
extern "C" void kernel_launch(void* const* d_in, const int* in_sizes, int n_in,
                              void* d_out, int out_size) {
    const float* x     = (const float*)d_in[0];
    const int*   ei    = (const int*)d_in[1];
    const int*   batch = (const int*)d_in[2];
    const float* Wl = (const float*)d_in[4];
    const float* bl = (const float*)d_in[5];
    const float* Wr = (const float*)d_in[6];
    const float* gw = (const float*)d_in[7];
    const float* gb = (const float*)d_in[8];
    const float* ms = (const float*)d_in[9];

    int n = in_sizes[0] / DD;
    int E = in_sizes[1] / 2;
    int nb = (n + 255) / 256;

    k_zero<<<(NN + 255) / 256, 256>>>();
    k_hist<<<(E + 255) / 256, 256>>>(ei, E);
    k_scan1<<<nb, 256>>>(batch, n);
    k_scan2<<<1, 256>>>(nb);
    k_scan3<<<nb, 256>>>(n);
    k_fill<<<(E + 255) / 256, 256>>>(ei, E);
    k_gather<<<((size_t)n * 32 + 255) / 256, 256>>>(x, n);
    k_mma<<<(n + 127) / 128, 512>>>(x, Wl, bl, Wr, batch, n);
    k_norm<<<1, 1024>>>(gw, gb, ms);
    k_out<<<(n * 32 + 255) / 256, 256>>>(x, batch, (float*)d_out, n);
}